// round 1
// baseline (speedup 1.0000x reference)
#include <cuda_runtime.h>
#include <cuda_bf16.h>
#include <cstdint>

#define N_NODES 400000
#define N_EDGES 1600000
#define HDIM 100
#define HDIM3 300
#define ADIM 50
#define CDIM 30
#define XPAD 101   // padded row stride in smem (odd -> conflict-free)

// ---------------- scratch (device globals; no allocation allowed) -------------
__device__ __align__(16) float g_h [N_NODES * HDIM];
__device__ __align__(16) float g_h2[N_NODES * HDIM];
__device__ __align__(16) float g_m [N_NODES * HDIM];
__device__ __align__(16) float g_msg[N_NODES * HDIM];
__device__ __align__(16) float g_gi[(size_t)N_NODES * HDIM3];
__device__ int g_row[N_EDGES];
__device__ int g_col[N_EDGES];
__device__ int g_is64;

// ---------------- math helpers ------------------------------------------------
__device__ __forceinline__ float fsigmoid(float x) {
    return 1.0f / (1.0f + __expf(-x));
}
__device__ __forceinline__ float ftanh_(float x) {
    float e = __expf(2.0f * x);          // exact formula tanh = (e^2x-1)/(e^2x+1)
    return 1.0f - 2.0f / (e + 1.0f);     // abs err ~1e-7, saturates correctly
}

// ---------------- edge dtype detection & normalization ------------------------
// If edges are int64, every odd 32-bit word is 0 (indices < 2^31). If int32,
// odd words are random node ids — P(all 32 zero) ~ 0.
__global__ void detect_kernel(const unsigned int* __restrict__ w) {
    unsigned int v = w[2 * threadIdx.x + 1];
    unsigned int any = __ballot_sync(0xffffffffu, v != 0u);
    if (threadIdx.x == 0) g_is64 = (any == 0u) ? 1 : 0;
}

__global__ void convert_kernel(const void* __restrict__ rp, const void* __restrict__ cp,
                               int* __restrict__ ro, int* __restrict__ co) {
    int e = blockIdx.x * blockDim.x + threadIdx.x;
    if (e >= N_EDGES) return;
    if (g_is64) {
        ro[e] = (int)((const long long*)rp)[e];
        co[e] = (int)((const long long*)cp)[e];
    } else {
        ro[e] = ((const int*)rp)[e];
        co[e] = ((const int*)cp)[e];
    }
}

// ---------------- h0 = features @ init_w + init_b  (N x 4 @ 4 x 100) ----------
__global__ void init_kernel(const float* __restrict__ f, const float* __restrict__ w,
                            const float* __restrict__ b, float* __restrict__ h) {
    __shared__ float sw[4 * HDIM];
    __shared__ float sb[HDIM];
    for (int i = threadIdx.x; i < 4 * HDIM; i += blockDim.x) sw[i] = w[i];
    for (int i = threadIdx.x; i < HDIM; i += blockDim.x) sb[i] = b[i];
    __syncthreads();
    int n = blockIdx.x * blockDim.x + threadIdx.x;
    if (n >= N_NODES) return;
    float f0 = f[n * 4 + 0], f1 = f[n * 4 + 1], f2 = f[n * 4 + 2], f3 = f[n * 4 + 3];
    float* o = h + (size_t)n * HDIM;
    #pragma unroll 4
    for (int d = 0; d < HDIM; d++) {
        o[d] = sb[d] + f0 * sw[d] + f1 * sw[HDIM + d] + f2 * sw[2 * HDIM + d] + f3 * sw[3 * HDIM + d];
    }
}

// ---------------- fused MLP: out = relu(X@w1+b1)@w2+b2  (100->50->100) --------
// dyn smem: w1(5000) w2(5000) b1(50) b2(100) + per-thread a-scratch 256*XPAD? No:
// a-scratch uses stride 51 region of size 256*51.
__global__ void __launch_bounds__(256) mlp_kernel(
    const float* __restrict__ X,
    const float* __restrict__ w1, const float* __restrict__ b1,
    const float* __restrict__ w2, const float* __restrict__ b2,
    float* __restrict__ out) {
    extern __shared__ float smem[];
    float* s1 = smem;                       // 100*50
    float* s2 = s1 + HDIM * ADIM;           // 50*100
    float* sb1 = s2 + ADIM * HDIM;          // 50
    float* sb2 = sb1 + ADIM;                // 100
    float* sa = sb2 + HDIM;                 // 256*51  (per-thread hidden scratch)
    for (int i = threadIdx.x; i < HDIM * ADIM; i += blockDim.x) { s1[i] = w1[i]; s2[i] = w2[i]; }
    for (int i = threadIdx.x; i < ADIM; i += blockDim.x) sb1[i] = b1[i];
    for (int i = threadIdx.x; i < HDIM; i += blockDim.x) sb2[i] = b2[i];
    __syncthreads();

    int n = blockIdx.x * 256 + threadIdx.x;
    if (n >= N_NODES) return;

    // layer 1: a[50] in registers, x streamed from global as float4
    float a[ADIM];
    #pragma unroll
    for (int j = 0; j < ADIM; j++) a[j] = sb1[j];
    const float4* xr = (const float4*)(X + (size_t)n * HDIM);
    for (int k4 = 0; k4 < HDIM / 4; k4++) {
        float4 v = xr[k4];
        const float* w0 = s1 + (k4 * 4 + 0) * ADIM;
        const float* w1r = s1 + (k4 * 4 + 1) * ADIM;
        const float* w2r = s1 + (k4 * 4 + 2) * ADIM;
        const float* w3r = s1 + (k4 * 4 + 3) * ADIM;
        #pragma unroll
        for (int j = 0; j < ADIM; j++) {
            a[j] = fmaf(v.x, w0[j], a[j]);
            a[j] = fmaf(v.y, w1r[j], a[j]);
            a[j] = fmaf(v.z, w2r[j], a[j]);
            a[j] = fmaf(v.w, w3r[j], a[j]);
        }
    }
    // relu + store hidden to per-thread smem (stride 51, conflict-free)
    float* as = sa + threadIdx.x * (ADIM + 1);
    #pragma unroll
    for (int j = 0; j < ADIM; j++) as[j] = fmaxf(a[j], 0.0f);

    // layer 2: 5 chunks of 20 outputs
    float* o = out + (size_t)n * HDIM;
    for (int cb = 0; cb < HDIM; cb += 20) {
        float acc[20];
        #pragma unroll
        for (int j = 0; j < 20; j++) acc[j] = sb2[cb + j];
        for (int k = 0; k < ADIM; k++) {
            float av = as[k];
            const float* wp = s2 + k * HDIM + cb;
            #pragma unroll
            for (int j = 0; j < 20; j++) acc[j] = fmaf(av, wp[j], acc[j]);
        }
        #pragma unroll
        for (int j = 0; j < 20; j++) o[cb + j] = acc[j];
    }
}

// ---------------- gi = X @ wih + bih  (100 -> 300) ----------------------------
// dyn smem: W 30000 + b 300 + x-tile 256*101
__global__ void __launch_bounds__(256) gru_gi_kernel(
    const float* __restrict__ X, const float* __restrict__ W,
    const float* __restrict__ B, float* __restrict__ out) {
    extern __shared__ float smem[];
    float* sw = smem;
    float* sb = sw + HDIM * HDIM3;
    float* sx = sb + HDIM3;
    for (int i = threadIdx.x; i < HDIM * HDIM3; i += 256) sw[i] = W[i];
    for (int i = threadIdx.x; i < HDIM3; i += 256) sb[i] = B[i];
    int base = blockIdx.x * 256;
    int nrows = min(256, N_NODES - base);
    int total = nrows * HDIM;
    for (int i = threadIdx.x * 4; i < total; i += 256 * 4) {
        float4 v = *(const float4*)(X + (size_t)base * HDIM + i);
        int r = i / HDIM, c = i - r * HDIM;
        float* p = sx + r * XPAD + c;
        p[0] = v.x; p[1] = v.y; p[2] = v.z; p[3] = v.w;
    }
    __syncthreads();
    int t = threadIdx.x;
    if (t >= nrows) return;
    const float* xs = sx + t * XPAD;
    float* o = out + (size_t)(base + t) * HDIM3;
    for (int cb = 0; cb < HDIM3; cb += 60) {
        float acc[60];
        #pragma unroll
        for (int j = 0; j < 60; j++) acc[j] = sb[cb + j];
        for (int k = 0; k < HDIM; k++) {
            float xv = xs[k];
            const float* wp = sw + k * HDIM3 + cb;
            #pragma unroll
            for (int j = 0; j < 60; j++) acc[j] = fmaf(xv, wp[j], acc[j]);
        }
        #pragma unroll
        for (int j = 0; j < 60; j++) o[cb + j] = acc[j];
    }
}

// ---------------- fused gh-gemm + GRU gate ------------------------------------
// hout = (1-z)*tanh(gi_n + r*gh_n) + z*h ; r/z from sigmoid(gi+gh)
// dyn smem: whh 30000 + bhh 300 + h-tile 256*101
__global__ void __launch_bounds__(256) gru_gate_kernel(
    const float* __restrict__ GI, const float* __restrict__ Hin,
    const float* __restrict__ W, const float* __restrict__ B,
    float* __restrict__ Hout) {
    extern __shared__ float smem[];
    float* sw = smem;
    float* sb = sw + HDIM * HDIM3;
    float* sx = sb + HDIM3;
    for (int i = threadIdx.x; i < HDIM * HDIM3; i += 256) sw[i] = W[i];
    for (int i = threadIdx.x; i < HDIM3; i += 256) sb[i] = B[i];
    int base = blockIdx.x * 256;
    int nrows = min(256, N_NODES - base);
    int total = nrows * HDIM;
    for (int i = threadIdx.x * 4; i < total; i += 256 * 4) {
        float4 v = *(const float4*)(Hin + (size_t)base * HDIM + i);
        int r = i / HDIM, c = i - r * HDIM;
        float* p = sx + r * XPAD + c;
        p[0] = v.x; p[1] = v.y; p[2] = v.z; p[3] = v.w;
    }
    __syncthreads();
    int t = threadIdx.x;
    if (t >= nrows) return;
    const float* hs = sx + t * XPAD;
    const float* gi = GI + (size_t)(base + t) * HDIM3;
    float* o = Hout + (size_t)(base + t) * HDIM;
    for (int d0 = 0; d0 < HDIM; d0 += 4) {
        float ar[4], az[4], an[4];
        #pragma unroll
        for (int j = 0; j < 4; j++) {
            ar[j] = sb[d0 + j];
            az[j] = sb[HDIM + d0 + j];
            an[j] = sb[2 * HDIM + d0 + j];
        }
        for (int k = 0; k < HDIM; k++) {
            float hv = hs[k];
            const float* wp = sw + k * HDIM3 + d0;
            #pragma unroll
            for (int j = 0; j < 4; j++) {
                ar[j] = fmaf(hv, wp[j], ar[j]);
                az[j] = fmaf(hv, wp[HDIM + j], az[j]);
                an[j] = fmaf(hv, wp[2 * HDIM + j], an[j]);
            }
        }
        float4 gr = *(const float4*)(gi + d0);
        float4 gz = *(const float4*)(gi + HDIM + d0);
        float4 gn = *(const float4*)(gi + 2 * HDIM + d0);
        float girv[4] = {gr.x, gr.y, gr.z, gr.w};
        float gizv[4] = {gz.x, gz.y, gz.z, gz.w};
        float ginv[4] = {gn.x, gn.y, gn.z, gn.w};
        #pragma unroll
        for (int j = 0; j < 4; j++) {
            float r = fsigmoid(girv[j] + ar[j]);
            float z = fsigmoid(gizv[j] + az[j]);
            float nn = ftanh_(ginv[j] + r * an[j]);
            o[d0 + j] = (1.0f - z) * nn + z * hs[d0 + j];
        }
    }
}

// ---------------- SpMM scatter: msg[dst[e]] += m[src[e]] ----------------------
// thread = (edge, float4-chunk); 25 chunks of 4 floats per 100-dim row
__global__ void spmm_kernel(const int* __restrict__ dst, const int* __restrict__ src,
                            const float* __restrict__ m, float* __restrict__ msg) {
    long long idx = (long long)blockIdx.x * blockDim.x + threadIdx.x;
    if (idx >= (long long)N_EDGES * 25) return;
    int e = (int)(idx / 25);
    int c = (int)(idx - (long long)e * 25);
    int d = dst[e];
    int s = src[e];
    float4 v = *(const float4*)(m + (size_t)s * HDIM + c * 4);
    float* p = msg + (size_t)d * HDIM + c * 4;
    asm volatile("red.global.add.v4.f32 [%0], {%1, %2, %3, %4};"
                 :: "l"(p), "f"(v.x), "f"(v.y), "f"(v.z), "f"(v.w)
                 : "memory");
}

// ---------------- classifier: out = relu(h@w1+b1)@w2+b2  (100->30->1) ---------
__global__ void __launch_bounds__(256) classify_kernel(
    const float* __restrict__ X,
    const float* __restrict__ w1, const float* __restrict__ b1,
    const float* __restrict__ w2, const float* __restrict__ b2,
    float* __restrict__ out) {
    __shared__ float s1[HDIM * CDIM];
    __shared__ float sb1[CDIM];
    __shared__ float s2[CDIM];
    __shared__ float sb2;
    for (int i = threadIdx.x; i < HDIM * CDIM; i += blockDim.x) s1[i] = w1[i];
    for (int i = threadIdx.x; i < CDIM; i += blockDim.x) { sb1[i] = b1[i]; s2[i] = w2[i]; }
    if (threadIdx.x == 0) sb2 = b2[0];
    __syncthreads();
    int n = blockIdx.x * blockDim.x + threadIdx.x;
    if (n >= N_NODES) return;
    float a[CDIM];
    #pragma unroll
    for (int j = 0; j < CDIM; j++) a[j] = sb1[j];
    const float4* xr = (const float4*)(X + (size_t)n * HDIM);
    for (int k4 = 0; k4 < HDIM / 4; k4++) {
        float4 v = xr[k4];
        const float* w0 = s1 + (k4 * 4 + 0) * CDIM;
        const float* w1r = s1 + (k4 * 4 + 1) * CDIM;
        const float* w2r = s1 + (k4 * 4 + 2) * CDIM;
        const float* w3r = s1 + (k4 * 4 + 3) * CDIM;
        #pragma unroll
        for (int j = 0; j < CDIM; j++) {
            a[j] = fmaf(v.x, w0[j], a[j]);
            a[j] = fmaf(v.y, w1r[j], a[j]);
            a[j] = fmaf(v.z, w2r[j], a[j]);
            a[j] = fmaf(v.w, w3r[j], a[j]);
        }
    }
    float r = sb2;
    #pragma unroll
    for (int j = 0; j < CDIM; j++) r = fmaf(fmaxf(a[j], 0.0f), s2[j], r);
    out[n] = r;
}

// ---------------- host orchestration -----------------------------------------
extern "C" void kernel_launch(void* const* d_in, const int* in_sizes, int n_in,
                              void* d_out, int out_size) {
    const float* features = (const float*)d_in[0];
    const void*  e_row    = d_in[1];
    const void*  e_col    = d_in[2];
    const float* init_w   = (const float*)d_in[3];
    const float* init_b   = (const float*)d_in[4];
    const float* fm_w1 = (const float*)d_in[5],  *fm_b1 = (const float*)d_in[6];
    const float* fm_w2 = (const float*)d_in[7],  *fm_b2 = (const float*)d_in[8];
    const float* bm_w1 = (const float*)d_in[9],  *bm_b1 = (const float*)d_in[10];
    const float* bm_w2 = (const float*)d_in[11], *bm_b2 = (const float*)d_in[12];
    const float* fg_wih = (const float*)d_in[13], *fg_whh = (const float*)d_in[14];
    const float* fg_bih = (const float*)d_in[15], *fg_bhh = (const float*)d_in[16];
    const float* bg_wih = (const float*)d_in[17], *bg_whh = (const float*)d_in[18];
    const float* bg_bih = (const float*)d_in[19], *bg_bhh = (const float*)d_in[20];
    const float* cl_w1 = (const float*)d_in[21], *cl_b1 = (const float*)d_in[22];
    const float* cl_w2 = (const float*)d_in[23], *cl_b2 = (const float*)d_in[24];
    float* out = (float*)d_out;

    float *h, *h2, *m, *msg, *gi;
    int *row_i, *col_i;
    cudaGetSymbolAddress((void**)&h,    g_h);
    cudaGetSymbolAddress((void**)&h2,   g_h2);
    cudaGetSymbolAddress((void**)&m,    g_m);
    cudaGetSymbolAddress((void**)&msg,  g_msg);
    cudaGetSymbolAddress((void**)&gi,   g_gi);
    cudaGetSymbolAddress((void**)&row_i, g_row);
    cudaGetSymbolAddress((void**)&col_i, g_col);

    const size_t smem_big = (size_t)(HDIM * HDIM3 + HDIM3 + 256 * XPAD) * sizeof(float); // 224624 B
    const size_t smem_mlp = (size_t)(HDIM * ADIM + ADIM * HDIM + ADIM + HDIM + 256 * (ADIM + 1)) * sizeof(float);
    cudaFuncSetAttribute(gru_gi_kernel,   cudaFuncAttributeMaxDynamicSharedMemorySize, (int)smem_big);
    cudaFuncSetAttribute(gru_gate_kernel, cudaFuncAttributeMaxDynamicSharedMemorySize, (int)smem_big);
    cudaFuncSetAttribute(mlp_kernel,      cudaFuncAttributeMaxDynamicSharedMemorySize, (int)smem_mlp);

    const int GN  = (N_NODES + 255) / 256;
    const int GE  = (N_EDGES + 255) / 256;
    const int GE25 = (int)(((long long)N_EDGES * 25 + 255) / 256);

    detect_kernel<<<1, 32>>>((const unsigned int*)e_row);
    convert_kernel<<<GE, 256>>>(e_row, e_col, row_i, col_i);
    init_kernel<<<GN, 256>>>(features, init_w, init_b, h);

    float* hc = h;
    float* hn = h2;
    const size_t msg_bytes = (size_t)N_NODES * HDIM * sizeof(float);

    for (int rnd = 0; rnd < 20; rnd++) {
        // forward pass
        mlp_kernel<<<GN, 256, smem_mlp>>>(hc, fm_w1, fm_b1, fm_w2, fm_b2, m);
        cudaMemsetAsync(msg, 0, msg_bytes);
        spmm_kernel<<<GE25, 256>>>(row_i, col_i, m, msg);   // msg[row] += m[col]
        gru_gi_kernel<<<GN, 256, smem_big>>>(msg, fg_wih, fg_bih, gi);
        gru_gate_kernel<<<GN, 256, smem_big>>>(gi, hc, fg_whh, fg_bhh, hn);
        { float* t = hc; hc = hn; hn = t; }
        // backward pass
        mlp_kernel<<<GN, 256, smem_mlp>>>(hc, bm_w1, bm_b1, bm_w2, bm_b2, m);
        cudaMemsetAsync(msg, 0, msg_bytes);
        spmm_kernel<<<GE25, 256>>>(col_i, row_i, m, msg);   // msg[col] += m[row]
        gru_gi_kernel<<<GN, 256, smem_big>>>(msg, bg_wih, bg_bih, gi);
        gru_gate_kernel<<<GN, 256, smem_big>>>(gi, hc, bg_whh, bg_bhh, hn);
        { float* t = hc; hc = hn; hn = t; }
    }

    classify_kernel<<<GN, 256>>>(hc, cl_w1, cl_b1, cl_w2, cl_b2, out);
}

// round 2
// speedup vs baseline: 1.2528x; 1.2528x over previous
#include <cuda_runtime.h>
#include <cuda_bf16.h>
#include <cstdint>

#define N_NODES 400000
#define N_EDGES 1600000
#define HDIM 100
#define HDIM3 300
#define ADIM 50
#define CDIM 30
#define XPAD 101   // padded row stride in smem (odd -> conflict-free)
#define TB 384     // threads per CTA for GEMM kernels (12 warps/SM)

typedef unsigned long long u64;

// ---------------- scratch (device globals; no allocation allowed) -------------
__device__ __align__(16) float g_h [N_NODES * HDIM];
__device__ __align__(16) float g_h2[N_NODES * HDIM];
__device__ __align__(16) float g_m [N_NODES * HDIM];
__device__ __align__(16) float g_msg[N_NODES * HDIM];
__device__ __align__(16) float g_gi[(size_t)N_NODES * HDIM3];
__device__ int g_row[N_EDGES];
__device__ int g_col[N_EDGES];
__device__ int g_is64;

// ---------------- packed f32x2 helpers (FFMA2: 2x fp32 throughput) ------------
__device__ __forceinline__ u64 pack2(float x, float y) {
    u64 r; asm("mov.b64 %0, {%1, %2};" : "=l"(r) : "f"(x), "f"(y)); return r;
}
__device__ __forceinline__ float2 unpack2(u64 v) {
    float2 r; asm("mov.b64 {%0, %1}, %2;" : "=f"(r.x), "=f"(r.y) : "l"(v)); return r;
}
__device__ __forceinline__ void fma2(u64& d, u64 a, u64 b) {
    asm("fma.rn.f32x2 %0, %1, %2, %0;" : "+l"(d) : "l"(a), "l"(b));
}

// ---------------- math helpers ------------------------------------------------
__device__ __forceinline__ float fsigmoid(float x) {
    return 1.0f / (1.0f + __expf(-x));
}
__device__ __forceinline__ float ftanh_(float x) {
    float e = __expf(2.0f * x);
    return 1.0f - 2.0f / (e + 1.0f);
}

// ---------------- edge dtype detection & normalization ------------------------
__global__ void detect_kernel(const unsigned int* __restrict__ w) {
    unsigned int v = w[2 * threadIdx.x + 1];
    unsigned int any = __ballot_sync(0xffffffffu, v != 0u);
    if (threadIdx.x == 0) g_is64 = (any == 0u) ? 1 : 0;
}

__global__ void convert_kernel(const void* __restrict__ rp, const void* __restrict__ cp,
                               int* __restrict__ ro, int* __restrict__ co) {
    int e = blockIdx.x * blockDim.x + threadIdx.x;
    if (e >= N_EDGES) return;
    if (g_is64) {
        ro[e] = (int)((const long long*)rp)[e];
        co[e] = (int)((const long long*)cp)[e];
    } else {
        ro[e] = ((const int*)rp)[e];
        co[e] = ((const int*)cp)[e];
    }
}

// ---------------- h0 = features @ init_w + init_b  (N x 4 @ 4 x 100) ----------
__global__ void init_kernel(const float* __restrict__ f, const float* __restrict__ w,
                            const float* __restrict__ b, float* __restrict__ h) {
    __shared__ float sw[4 * HDIM];
    __shared__ float sb[HDIM];
    for (int i = threadIdx.x; i < 4 * HDIM; i += blockDim.x) sw[i] = w[i];
    for (int i = threadIdx.x; i < HDIM; i += blockDim.x) sb[i] = b[i];
    __syncthreads();
    int n = blockIdx.x * blockDim.x + threadIdx.x;
    if (n >= N_NODES) return;
    float f0 = f[n * 4 + 0], f1 = f[n * 4 + 1], f2 = f[n * 4 + 2], f3 = f[n * 4 + 3];
    float* o = h + (size_t)n * HDIM;
    #pragma unroll 4
    for (int d = 0; d < HDIM; d++) {
        o[d] = sb[d] + f0 * sw[d] + f1 * sw[HDIM + d] + f2 * sw[2 * HDIM + d] + f3 * sw[3 * HDIM + d];
    }
}

// ---------------- fused MLP: out = relu(X@w1+b1)@w2+b2  (100->50->100) --------
__global__ void __launch_bounds__(TB) mlp_kernel(
    const float* __restrict__ X,
    const float* __restrict__ w1, const float* __restrict__ b1,
    const float* __restrict__ w2, const float* __restrict__ b2,
    float* __restrict__ out) {
    extern __shared__ float smem[];
    float* s1  = smem;            // 100*50
    float* s2  = s1 + 5000;       // 50*100
    float* sb1 = s2 + 5000;       // 50   (byte off 40000, 8B-aligned)
    float* sb2 = sb1 + 50;        // 100  (byte off 40200, 8B-aligned)
    float* sx  = sb2 + 100;       // TB*101
    for (int i = threadIdx.x; i < 5000; i += TB) { s1[i] = w1[i]; s2[i] = w2[i]; }
    for (int i = threadIdx.x; i < ADIM; i += TB) sb1[i] = b1[i];
    for (int i = threadIdx.x; i < HDIM; i += TB) sb2[i] = b2[i];

    int base = blockIdx.x * TB;
    int nrows = min(TB, N_NODES - base);
    int total = nrows * HDIM;
    for (int i = threadIdx.x * 4; i < total; i += TB * 4) {
        float4 v = *(const float4*)(X + (size_t)base * HDIM + i);
        int r = i / HDIM, c = i - r * HDIM;
        float* p = sx + r * XPAD + c;
        p[0] = v.x; p[1] = v.y; p[2] = v.z; p[3] = v.w;
    }
    __syncthreads();

    int t = threadIdx.x;
    if (t >= nrows) return;
    float* xs = sx + t * XPAD;

    // ---- layer 1: 50 outputs = 25 packed accums ----
    u64 a[25];
    const u64* bb1 = (const u64*)sb1;
    #pragma unroll
    for (int j = 0; j < 25; j++) a[j] = bb1[j];
    for (int k = 0; k < HDIM; k++) {
        float xv = xs[k];
        u64 x2 = pack2(xv, xv);
        const ulonglong2* wp = (const ulonglong2*)(s1 + k * ADIM);
        #pragma unroll
        for (int j = 0; j < 12; j++) {
            ulonglong2 w = wp[j];
            fma2(a[2 * j],     x2, w.x);
            fma2(a[2 * j + 1], x2, w.y);
        }
        fma2(a[24], x2, ((const u64*)(s1 + k * ADIM))[24]);
    }
    // relu -> store hidden into own x row (x consumed; no cross-thread access)
    #pragma unroll
    for (int j = 0; j < 25; j++) {
        float2 v = unpack2(a[j]);
        xs[2 * j]     = fmaxf(v.x, 0.0f);
        xs[2 * j + 1] = fmaxf(v.y, 0.0f);
    }

    // ---- layer 2: 100 outputs = 50 packed accums ----
    u64 c[50];
    const u64* bb2 = (const u64*)sb2;
    #pragma unroll
    for (int j = 0; j < 50; j++) c[j] = bb2[j];
    for (int k = 0; k < ADIM; k++) {
        float av = xs[k];
        u64 a2 = pack2(av, av);
        const ulonglong2* wp = (const ulonglong2*)(s2 + k * HDIM);
        #pragma unroll
        for (int j = 0; j < 25; j++) {
            ulonglong2 w = wp[j];
            fma2(c[2 * j],     a2, w.x);
            fma2(c[2 * j + 1], a2, w.y);
        }
    }
    float* o = out + (size_t)(base + t) * HDIM;
    #pragma unroll
    for (int j = 0; j < 25; j++) {
        float2 v0 = unpack2(c[2 * j]);
        float2 v1 = unpack2(c[2 * j + 1]);
        *(float4*)(o + 4 * j) = make_float4(v0.x, v0.y, v1.x, v1.y);
    }
}

// ---------------- gi = X @ wih + bih  (100 -> 300), W streamed in 100-col chunks
__global__ void __launch_bounds__(TB) gru_gi_kernel(
    const float* __restrict__ X, const float* __restrict__ W,
    const float* __restrict__ B, float* __restrict__ out) {
    extern __shared__ float smem[];
    float* sw = smem;             // 100*100 chunk
    float* sb = sw + 10000;       // 300
    float* sx = sb + 300;         // TB*101
    int base = blockIdx.x * TB;
    int nrows = min(TB, N_NODES - base);
    for (int i = threadIdx.x; i < HDIM3; i += TB) sb[i] = B[i];
    int total = nrows * HDIM;
    for (int i = threadIdx.x * 4; i < total; i += TB * 4) {
        float4 v = *(const float4*)(X + (size_t)base * HDIM + i);
        int r = i / HDIM, c = i - r * HDIM;
        float* p = sx + r * XPAD + c;
        p[0] = v.x; p[1] = v.y; p[2] = v.z; p[3] = v.w;
    }
    int t = threadIdx.x;
    const float* xs = sx + t * XPAD;

    for (int ch = 0; ch < 3; ch++) {
        int c0 = ch * 100;
        __syncthreads();   // tile ready / previous chunk compute done
        for (int i = threadIdx.x * 4; i < 100 * 100; i += TB * 4) {
            int k = i / 100, j = i - k * 100;
            *(float4*)(sw + i) = *(const float4*)(W + k * HDIM3 + c0 + j);
        }
        __syncthreads();
        if (t < nrows) {
            u64 acc[50];
            const u64* bb = (const u64*)(sb + c0);
            #pragma unroll
            for (int j = 0; j < 50; j++) acc[j] = bb[j];
            for (int k = 0; k < HDIM; k++) {
                float xv = xs[k];
                u64 x2 = pack2(xv, xv);
                const ulonglong2* wp = (const ulonglong2*)(sw + k * 100);
                #pragma unroll
                for (int j = 0; j < 25; j++) {
                    ulonglong2 w = wp[j];
                    fma2(acc[2 * j],     x2, w.x);
                    fma2(acc[2 * j + 1], x2, w.y);
                }
            }
            float* o = out + (size_t)(base + t) * HDIM3 + c0;
            #pragma unroll
            for (int j = 0; j < 25; j++) {
                float2 v0 = unpack2(acc[2 * j]);
                float2 v1 = unpack2(acc[2 * j + 1]);
                *(float4*)(o + 4 * j) = make_float4(v0.x, v0.y, v1.x, v1.y);
            }
        }
    }
}

// ---------------- fused gh-gemm + GRU gate, 20-col chunks across all 3 gates --
__global__ void __launch_bounds__(TB) gru_gate_kernel(
    const float* __restrict__ GI, const float* __restrict__ Hin,
    const float* __restrict__ W, const float* __restrict__ B,
    float* __restrict__ Hout) {
    extern __shared__ float smem[];
    float* sw = smem;             // 100 x (3 strips of 20) = 6000
    float* sb = sw + 6000;        // 300
    float* sx = sb + 300;         // TB*101
    int base = blockIdx.x * TB;
    int nrows = min(TB, N_NODES - base);
    for (int i = threadIdx.x; i < HDIM3; i += TB) sb[i] = B[i];
    int total = nrows * HDIM;
    for (int i = threadIdx.x * 4; i < total; i += TB * 4) {
        float4 v = *(const float4*)(Hin + (size_t)base * HDIM + i);
        int r = i / HDIM, c = i - r * HDIM;
        float* p = sx + r * XPAD + c;
        p[0] = v.x; p[1] = v.y; p[2] = v.z; p[3] = v.w;
    }
    int t = threadIdx.x;
    const float* hs = sx + t * XPAD;

    for (int ch = 0; ch < 5; ch++) {
        int d0 = ch * 20;
        __syncthreads();
        for (int i = threadIdx.x * 4; i < 100 * 60; i += TB * 4) {
            int k = i / 60, rem = i - k * 60;
            int g = rem / 20, j = rem - g * 20;
            *(float4*)(sw + i) = *(const float4*)(W + k * HDIM3 + g * HDIM + d0 + j);
        }
        __syncthreads();
        if (t < nrows) {
            u64 ar[10], az[10], an[10];
            const u64* br = (const u64*)(sb + d0);
            const u64* bz = (const u64*)(sb + HDIM + d0);
            const u64* bn = (const u64*)(sb + 2 * HDIM + d0);
            #pragma unroll
            for (int j = 0; j < 10; j++) { ar[j] = br[j]; az[j] = bz[j]; an[j] = bn[j]; }
            for (int k = 0; k < HDIM; k++) {
                float hv = hs[k];
                u64 h2 = pack2(hv, hv);
                const ulonglong2* w0 = (const ulonglong2*)(sw + k * 60);
                const ulonglong2* w1 = (const ulonglong2*)(sw + k * 60 + 20);
                const ulonglong2* w2 = (const ulonglong2*)(sw + k * 60 + 40);
                #pragma unroll
                for (int j = 0; j < 5; j++) {
                    ulonglong2 wa = w0[j], wb = w1[j], wc = w2[j];
                    fma2(ar[2 * j],     h2, wa.x);
                    fma2(ar[2 * j + 1], h2, wa.y);
                    fma2(az[2 * j],     h2, wb.x);
                    fma2(az[2 * j + 1], h2, wb.y);
                    fma2(an[2 * j],     h2, wc.x);
                    fma2(an[2 * j + 1], h2, wc.y);
                }
            }
            const float* gi = GI + (size_t)(base + t) * HDIM3;
            float* o = Hout + (size_t)(base + t) * HDIM;
            #pragma unroll
            for (int j = 0; j < 10; j++) {
                int d = d0 + 2 * j;
                float2 gr = *(const float2*)(gi + d);
                float2 gz = *(const float2*)(gi + HDIM + d);
                float2 gn = *(const float2*)(gi + 2 * HDIM + d);
                float2 hr = unpack2(ar[j]);
                float2 hz = unpack2(az[j]);
                float2 hn = unpack2(an[j]);
                float r0 = fsigmoid(gr.x + hr.x), r1 = fsigmoid(gr.y + hr.y);
                float z0 = fsigmoid(gz.x + hz.x), z1 = fsigmoid(gz.y + hz.y);
                float n0 = ftanh_(gn.x + r0 * hn.x), n1 = ftanh_(gn.y + r1 * hn.y);
                float h0 = hs[d], h1 = hs[d + 1];
                *(float2*)(o + d) = make_float2((1.0f - z0) * n0 + z0 * h0,
                                                (1.0f - z1) * n1 + z1 * h1);
            }
        }
    }
}

// ---------------- SpMM scatter: msg[dst[e]] += m[src[e]] ----------------------
__global__ void spmm_kernel(const int* __restrict__ dst, const int* __restrict__ src,
                            const float* __restrict__ m, float* __restrict__ msg) {
    long long idx = (long long)blockIdx.x * blockDim.x + threadIdx.x;
    if (idx >= (long long)N_EDGES * 25) return;
    int e = (int)(idx / 25);
    int c = (int)(idx - (long long)e * 25);
    int d = dst[e];
    int s = src[e];
    float4 v = *(const float4*)(m + (size_t)s * HDIM + c * 4);
    float* p = msg + (size_t)d * HDIM + c * 4;
    asm volatile("red.global.add.v4.f32 [%0], {%1, %2, %3, %4};"
                 :: "l"(p), "f"(v.x), "f"(v.y), "f"(v.z), "f"(v.w)
                 : "memory");
}

// ---------------- classifier: out = relu(h@w1+b1)@w2+b2  (100->30->1) ---------
__global__ void __launch_bounds__(256) classify_kernel(
    const float* __restrict__ X,
    const float* __restrict__ w1, const float* __restrict__ b1,
    const float* __restrict__ w2, const float* __restrict__ b2,
    float* __restrict__ out) {
    __shared__ float s1[HDIM * CDIM];
    __shared__ float sb1[CDIM];
    __shared__ float s2[CDIM];
    __shared__ float sb2;
    for (int i = threadIdx.x; i < HDIM * CDIM; i += blockDim.x) s1[i] = w1[i];
    for (int i = threadIdx.x; i < CDIM; i += blockDim.x) { sb1[i] = b1[i]; s2[i] = w2[i]; }
    if (threadIdx.x == 0) sb2 = b2[0];
    __syncthreads();
    int n = blockIdx.x * blockDim.x + threadIdx.x;
    if (n >= N_NODES) return;
    float a[CDIM];
    #pragma unroll
    for (int j = 0; j < CDIM; j++) a[j] = sb1[j];
    const float4* xr = (const float4*)(X + (size_t)n * HDIM);
    for (int k4 = 0; k4 < HDIM / 4; k4++) {
        float4 v = xr[k4];
        const float* w0 = s1 + (k4 * 4 + 0) * CDIM;
        const float* w1r = s1 + (k4 * 4 + 1) * CDIM;
        const float* w2r = s1 + (k4 * 4 + 2) * CDIM;
        const float* w3r = s1 + (k4 * 4 + 3) * CDIM;
        #pragma unroll
        for (int j = 0; j < CDIM; j++) {
            a[j] = fmaf(v.x, w0[j], a[j]);
            a[j] = fmaf(v.y, w1r[j], a[j]);
            a[j] = fmaf(v.z, w2r[j], a[j]);
            a[j] = fmaf(v.w, w3r[j], a[j]);
        }
    }
    float r = sb2;
    #pragma unroll
    for (int j = 0; j < CDIM; j++) r = fmaf(fmaxf(a[j], 0.0f), s2[j], r);
    out[n] = r;
}

// ---------------- host orchestration -----------------------------------------
extern "C" void kernel_launch(void* const* d_in, const int* in_sizes, int n_in,
                              void* d_out, int out_size) {
    const float* features = (const float*)d_in[0];
    const void*  e_row    = d_in[1];
    const void*  e_col    = d_in[2];
    const float* init_w   = (const float*)d_in[3];
    const float* init_b   = (const float*)d_in[4];
    const float* fm_w1 = (const float*)d_in[5],  *fm_b1 = (const float*)d_in[6];
    const float* fm_w2 = (const float*)d_in[7],  *fm_b2 = (const float*)d_in[8];
    const float* bm_w1 = (const float*)d_in[9],  *bm_b1 = (const float*)d_in[10];
    const float* bm_w2 = (const float*)d_in[11], *bm_b2 = (const float*)d_in[12];
    const float* fg_wih = (const float*)d_in[13], *fg_whh = (const float*)d_in[14];
    const float* fg_bih = (const float*)d_in[15], *fg_bhh = (const float*)d_in[16];
    const float* bg_wih = (const float*)d_in[17], *bg_whh = (const float*)d_in[18];
    const float* bg_bih = (const float*)d_in[19], *bg_bhh = (const float*)d_in[20];
    const float* cl_w1 = (const float*)d_in[21], *cl_b1 = (const float*)d_in[22];
    const float* cl_w2 = (const float*)d_in[23], *cl_b2 = (const float*)d_in[24];
    float* out = (float*)d_out;

    float *h, *h2, *m, *msg, *gi;
    int *row_i, *col_i;
    cudaGetSymbolAddress((void**)&h,    g_h);
    cudaGetSymbolAddress((void**)&h2,   g_h2);
    cudaGetSymbolAddress((void**)&m,    g_m);
    cudaGetSymbolAddress((void**)&msg,  g_msg);
    cudaGetSymbolAddress((void**)&gi,   g_gi);
    cudaGetSymbolAddress((void**)&row_i, g_row);
    cudaGetSymbolAddress((void**)&col_i, g_col);

    const size_t smem_gi   = (size_t)(10000 + 300 + TB * XPAD) * sizeof(float); // 196,336
    const size_t smem_gate = (size_t)(6000  + 300 + TB * XPAD) * sizeof(float); // 180,336
    const size_t smem_mlp  = (size_t)(5000 + 5000 + 50 + 100 + TB * XPAD) * sizeof(float); // 195,736
    cudaFuncSetAttribute(gru_gi_kernel,   cudaFuncAttributeMaxDynamicSharedMemorySize, (int)smem_gi);
    cudaFuncSetAttribute(gru_gate_kernel, cudaFuncAttributeMaxDynamicSharedMemorySize, (int)smem_gate);
    cudaFuncSetAttribute(mlp_kernel,      cudaFuncAttributeMaxDynamicSharedMemorySize, (int)smem_mlp);

    const int GN256 = (N_NODES + 255) / 256;
    const int GNTB  = (N_NODES + TB - 1) / TB;
    const int GE    = (N_EDGES + 255) / 256;
    const int GE25  = (int)(((long long)N_EDGES * 25 + 255) / 256);

    detect_kernel<<<1, 32>>>((const unsigned int*)e_row);
    convert_kernel<<<GE, 256>>>(e_row, e_col, row_i, col_i);
    init_kernel<<<GN256, 256>>>(features, init_w, init_b, h);

    float* hc = h;
    float* hn = h2;
    const size_t msg_bytes = (size_t)N_NODES * HDIM * sizeof(float);

    for (int rnd = 0; rnd < 20; rnd++) {
        // forward pass
        mlp_kernel<<<GNTB, TB, smem_mlp>>>(hc, fm_w1, fm_b1, fm_w2, fm_b2, m);
        cudaMemsetAsync(msg, 0, msg_bytes);
        spmm_kernel<<<GE25, 256>>>(row_i, col_i, m, msg);   // msg[row] += m[col]
        gru_gi_kernel<<<GNTB, TB, smem_gi>>>(msg, fg_wih, fg_bih, gi);
        gru_gate_kernel<<<GNTB, TB, smem_gate>>>(gi, hc, fg_whh, fg_bhh, hn);
        { float* t = hc; hc = hn; hn = t; }
        // backward pass
        mlp_kernel<<<GNTB, TB, smem_mlp>>>(hc, bm_w1, bm_b1, bm_w2, bm_b2, m);
        cudaMemsetAsync(msg, 0, msg_bytes);
        spmm_kernel<<<GE25, 256>>>(col_i, row_i, m, msg);   // msg[col] += m[row]
        gru_gi_kernel<<<GNTB, TB, smem_gi>>>(msg, bg_wih, bg_bih, gi);
        gru_gate_kernel<<<GNTB, TB, smem_gate>>>(gi, hc, bg_whh, bg_bhh, hn);
        { float* t = hc; hc = hn; hn = t; }
    }

    classify_kernel<<<GN256, 256>>>(hc, cl_w1, cl_b1, cl_w2, cl_b2, out);
}

// round 3
// speedup vs baseline: 1.9735x; 1.5754x over previous
#include <cuda_runtime.h>
#include <cuda_bf16.h>
#include <cstdint>

#define N_NODES 400000
#define N_EDGES 1600000
#define HDIM 100
#define HDIM3 300
#define ADIM 50
#define CDIM 30
#define GTB 320          // threads for tiled GEMM kernels (10 warps)
#define MTILE 128        // rows per CTA (400000 = 128 * 3125 exactly)
#define SXS 132          // k-major tile row stride (16B-aligned, conflict-free)

typedef unsigned long long u64;

// ---------------- scratch (device globals) -------------------------------------
// h, h2, gi are stored TRANSPOSED: [dim][node]. m, msg stay row-major [node][dim].
__device__ __align__(16) float g_h [N_NODES * HDIM];
__device__ __align__(16) float g_h2[N_NODES * HDIM];
__device__ __align__(16) float g_m [N_NODES * HDIM];
__device__ __align__(16) float g_msg[N_NODES * HDIM];
__device__ __align__(16) float g_gi[(size_t)N_NODES * HDIM3];
__device__ int g_row[N_EDGES];
__device__ int g_col[N_EDGES];
__device__ int g_is64;

// ---------------- packed f32x2 helpers -----------------------------------------
__device__ __forceinline__ u64 pack2(float x, float y) {
    u64 r; asm("mov.b64 %0, {%1, %2};" : "=l"(r) : "f"(x), "f"(y)); return r;
}
__device__ __forceinline__ float2 unpack2(u64 v) {
    float2 r; asm("mov.b64 {%0, %1}, %2;" : "=f"(r.x), "=f"(r.y) : "l"(v)); return r;
}
__device__ __forceinline__ void fma2(u64& d, u64 a, u64 b) {
    asm("fma.rn.f32x2 %0, %1, %2, %0;" : "+l"(d) : "l"(a), "l"(b));
}

__device__ __forceinline__ float fsigmoid(float x) { return 1.0f / (1.0f + __expf(-x)); }
__device__ __forceinline__ float ftanh_(float x) {
    float e = __expf(2.0f * x);
    return 1.0f - 2.0f / (e + 1.0f);
}

// ---------------- edge dtype detection & normalization -------------------------
__global__ void detect_kernel(const unsigned int* __restrict__ w) {
    unsigned int v = w[2 * threadIdx.x + 1];
    unsigned int any = __ballot_sync(0xffffffffu, v != 0u);
    if (threadIdx.x == 0) g_is64 = (any == 0u) ? 1 : 0;
}

__global__ void convert_kernel(const void* __restrict__ rp, const void* __restrict__ cp,
                               int* __restrict__ ro, int* __restrict__ co) {
    int e = blockIdx.x * blockDim.x + threadIdx.x;
    if (e >= N_EDGES) return;
    if (g_is64) {
        ro[e] = (int)((const long long*)rp)[e];
        co[e] = (int)((const long long*)cp)[e];
    } else {
        ro[e] = ((const int*)rp)[e];
        co[e] = ((const int*)cp)[e];
    }
}

// ---------------- h0_T[d][n] = (features @ init_w + init_b)^T ------------------
__global__ void initT_kernel(const float* __restrict__ f, const float* __restrict__ w,
                             const float* __restrict__ b, float* __restrict__ hT) {
    __shared__ float sw[4 * HDIM];
    __shared__ float sb[HDIM];
    for (int i = threadIdx.x; i < 4 * HDIM; i += blockDim.x) sw[i] = w[i];
    for (int i = threadIdx.x; i < HDIM; i += blockDim.x) sb[i] = b[i];
    __syncthreads();
    int n = blockIdx.x * blockDim.x + threadIdx.x;
    float4 fv = *(const float4*)(f + (size_t)n * 4);
    #pragma unroll 4
    for (int d = 0; d < HDIM; d++) {
        float v = sb[d] + fv.x * sw[d] + fv.y * sw[HDIM + d]
                        + fv.z * sw[2 * HDIM + d] + fv.w * sw[3 * HDIM + d];
        hT[(size_t)d * N_NODES + n] = v;   // coalesced across lanes
    }
}

// ---------------- tiled MLP: m = relu(hT^T @ w1 + b1) @ w2 + b2 (row-major out)
__global__ void __launch_bounds__(GTB, 2) mlp_tiled(
    const float* __restrict__ HT,
    const float* __restrict__ w1, const float* __restrict__ b1,
    const float* __restrict__ w2, const float* __restrict__ b2,
    float* __restrict__ Mout) {
    extern __shared__ float sm[];
    float* sxT = sm;            // 100 x 132 (reused: x tile -> hidden tile -> out tile)
    float* sw1 = sm + HDIM * SXS;     // 5000
    float* sw2 = sw1 + 5000;          // 5000
    float* sb  = sw2 + 5000;          // 150 (b1 | b2)
    int base = blockIdx.x * MTILE;
    int lane = threadIdx.x & 31, wid = threadIdx.x >> 5;

    for (int i = threadIdx.x; i < 5000; i += GTB) { sw1[i] = w1[i]; sw2[i] = w2[i]; }
    if (threadIdx.x < 50) sb[threadIdx.x] = b1[threadIdx.x];
    else if (threadIdx.x < 150) sb[threadIdx.x] = b2[threadIdx.x - 50];
    // stage x tile (k-major, coalesced from transposed global)
    for (int idx = threadIdx.x; idx < HDIM * 32; idx += GTB) {
        int k = idx >> 5, rq = idx & 31;
        *(float4*)(sxT + k * SXS + rq * 4) =
            *(const float4*)(HT + (size_t)k * N_NODES + base + rq * 4);
    }
    __syncthreads();

    // layer 1: thread tile 4 rows x 5 cols (scalar accum)
    float a1[4][5];
    #pragma unroll
    for (int r = 0; r < 4; r++)
        #pragma unroll
        for (int j = 0; j < 5; j++) a1[r][j] = sb[wid * 5 + j];
    const float* xp = sxT + lane * 4;
    for (int k = 0; k < HDIM; k++) {
        float4 a = *(const float4*)(xp + k * SXS);
        const float* wr = sw1 + k * ADIM + wid * 5;
        #pragma unroll
        for (int j = 0; j < 5; j++) {
            float wv = wr[j];
            a1[0][j] = fmaf(a.x, wv, a1[0][j]);
            a1[1][j] = fmaf(a.y, wv, a1[1][j]);
            a1[2][j] = fmaf(a.z, wv, a1[2][j]);
            a1[3][j] = fmaf(a.w, wv, a1[3][j]);
        }
    }
    __syncthreads();   // x tile reads complete
    #pragma unroll
    for (int j = 0; j < 5; j++)
        #pragma unroll
        for (int r = 0; r < 4; r++)
            sxT[(wid * 5 + j) * SXS + lane * 4 + r] = fmaxf(a1[r][j], 0.0f);
    __syncthreads();

    // layer 2: K=50, thread tile 4 rows x 10 cols (packed)
    u64 acc[20];
    const u64* bb = (const u64*)(sb + 50 + wid * 10);
    #pragma unroll
    for (int r = 0; r < 4; r++)
        #pragma unroll
        for (int j = 0; j < 5; j++) acc[r * 5 + j] = bb[j];
    for (int k = 0; k < ADIM; k++) {
        float4 a = *(const float4*)(xp + k * SXS);
        u64 a0 = pack2(a.x, a.x), a1p = pack2(a.y, a.y);
        u64 a2 = pack2(a.z, a.z), a3 = pack2(a.w, a.w);
        const float* wr = sw2 + k * HDIM + wid * 10;
        #pragma unroll
        for (int j = 0; j < 5; j++) {
            u64 wv = *(const u64*)(wr + 2 * j);
            fma2(acc[j],      a0,  wv);
            fma2(acc[5 + j],  a1p, wv);
            fma2(acc[10 + j], a2,  wv);
            fma2(acc[15 + j], a3,  wv);
        }
    }
    __syncthreads();   // hidden tile reads complete
    // stage output tile transposed in smem: mT[c][row]
    #pragma unroll
    for (int j = 0; j < 5; j++) {
        int c = wid * 10 + 2 * j;
        #pragma unroll
        for (int r = 0; r < 4; r++) {
            float2 v = unpack2(acc[r * 5 + j]);
            sxT[c * SXS + lane * 4 + r]       = v.x;
            sxT[(c + 1) * SXS + lane * 4 + r] = v.y;
        }
    }
    __syncthreads();
    // copy out row-major
    for (int idx = threadIdx.x; idx < 25 * MTILE; idx += GTB) {
        int row = idx & 127, c4 = (idx >> 7) * 4;
        float4 v = make_float4(sxT[c4 * SXS + row], sxT[(c4 + 1) * SXS + row],
                               sxT[(c4 + 2) * SXS + row], sxT[(c4 + 3) * SXS + row]);
        *(float4*)(Mout + (size_t)(base + row) * HDIM + c4) = v;
    }
}

// ---------------- tiled gi: giT = (msg @ wih + bih)^T ---------------------------
__global__ void __launch_bounds__(GTB, 2) gi_tiled(
    const float* __restrict__ MSG,   // row-major [N][100]
    const float* __restrict__ W, const float* __restrict__ B,
    float* __restrict__ outT) {      // [300][N]
    extern __shared__ float sm[];
    float* sxT = sm;                 // 100 x 132
    float* sw  = sm + HDIM * SXS;    // 100 x 100 chunk
    float* sb  = sw + 10000;         // 300
    int base = blockIdx.x * MTILE;
    int lane = threadIdx.x & 31, wid = threadIdx.x >> 5;
    for (int i = threadIdx.x; i < HDIM3; i += GTB) sb[i] = B[i];
    // stage msg (row-major) -> k-major tile; idx = kq*128 + row keeps STS conflict-free
    for (int idx = threadIdx.x; idx < 25 * MTILE; idx += GTB) {
        int kq = idx >> 7, row = idx & 127;
        float4 v = *(const float4*)(MSG + (size_t)(base + row) * HDIM + kq * 4);
        float* p = sxT + (kq * 4) * SXS + row;
        p[0] = v.x; p[SXS] = v.y; p[2 * SXS] = v.z; p[3 * SXS] = v.w;
    }
    const float* xp = sxT + lane * 4;
    for (int ch = 0; ch < 3; ch++) {
        int c0 = ch * 100;
        __syncthreads();
        for (int i = threadIdx.x * 4; i < 10000; i += GTB * 4) {
            int k = i / 100, j = i - k * 100;
            *(float4*)(sw + i) = *(const float4*)(W + (size_t)k * HDIM3 + c0 + j);
        }
        __syncthreads();
        u64 acc[20];
        const u64* bb = (const u64*)(sb + c0 + wid * 10);
        #pragma unroll
        for (int r = 0; r < 4; r++)
            #pragma unroll
            for (int j = 0; j < 5; j++) acc[r * 5 + j] = bb[j];
        const float* wp = sw + wid * 10;
        for (int k = 0; k < HDIM; k++) {
            float4 a = *(const float4*)(xp + k * SXS);
            u64 a0 = pack2(a.x, a.x), a1p = pack2(a.y, a.y);
            u64 a2 = pack2(a.z, a.z), a3 = pack2(a.w, a.w);
            const float* wr = wp + k * 100;
            #pragma unroll
            for (int j = 0; j < 5; j++) {
                u64 wv = *(const u64*)(wr + 2 * j);
                fma2(acc[j],      a0,  wv);
                fma2(acc[5 + j],  a1p, wv);
                fma2(acc[10 + j], a2,  wv);
                fma2(acc[15 + j], a3,  wv);
            }
        }
        size_t rowoff = base + lane * 4;
        #pragma unroll
        for (int j = 0; j < 5; j++) {
            int c = c0 + wid * 10 + 2 * j;
            float2 v0 = unpack2(acc[j]);
            float2 v1 = unpack2(acc[5 + j]);
            float2 v2 = unpack2(acc[10 + j]);
            float2 v3 = unpack2(acc[15 + j]);
            *(float4*)(outT + (size_t)c * N_NODES + rowoff) =
                make_float4(v0.x, v1.x, v2.x, v3.x);
            *(float4*)(outT + (size_t)(c + 1) * N_NODES + rowoff) =
                make_float4(v0.y, v1.y, v2.y, v3.y);
        }
    }
}

// ---------------- tiled gate: h' = GRU(giT, hT) (all transposed) ----------------
__global__ void __launch_bounds__(GTB, 2) gate_tiled(
    const float* __restrict__ GIT,   // [300][N]
    const float* __restrict__ HT,    // [100][N]
    const float* __restrict__ W, const float* __restrict__ B,
    float* __restrict__ HoutT) {     // [100][N]
    extern __shared__ float sm[];
    float* sxT = sm;                 // 100 x 132 (old h, k-major)
    float* sw  = sm + HDIM * SXS;    // 100 x 60 chunk (3 gates x 20 cols)
    float* sb  = sw + 6000;          // 300
    int base = blockIdx.x * MTILE;
    int lane = threadIdx.x & 31, wid = threadIdx.x >> 5;
    for (int i = threadIdx.x; i < HDIM3; i += GTB) sb[i] = B[i];
    for (int idx = threadIdx.x; idx < HDIM * 32; idx += GTB) {
        int k = idx >> 5, rq = idx & 31;
        *(float4*)(sxT + k * SXS + rq * 4) =
            *(const float4*)(HT + (size_t)k * N_NODES + base + rq * 4);
    }
    const float* xp = sxT + lane * 4;
    size_t rowoff = base + lane * 4;
    for (int ch = 0; ch < 5; ch++) {
        int d0 = ch * 20;
        __syncthreads();
        for (int i = threadIdx.x * 4; i < 6000; i += GTB * 4) {
            int k = i / 60, rem = i - k * 60;
            int g = rem / 20, j = rem - g * 20;
            *(float4*)(sw + i) = *(const float4*)(W + (size_t)k * HDIM3 + g * HDIM + d0 + j);
        }
        __syncthreads();
        int cl = wid * 2;
        u64 ar[4], az[4], an[4];
        {
            u64 br = *(const u64*)(sb + d0 + cl);
            u64 bz = *(const u64*)(sb + HDIM + d0 + cl);
            u64 bn = *(const u64*)(sb + 2 * HDIM + d0 + cl);
            #pragma unroll
            for (int r = 0; r < 4; r++) { ar[r] = br; az[r] = bz; an[r] = bn; }
        }
        for (int k = 0; k < HDIM; k++) {
            float4 a = *(const float4*)(xp + k * SXS);
            u64 a0 = pack2(a.x, a.x), a1p = pack2(a.y, a.y);
            u64 a2 = pack2(a.z, a.z), a3 = pack2(a.w, a.w);
            const float* wr = sw + k * 60 + cl;
            u64 wrv = *(const u64*)(wr);
            u64 wzv = *(const u64*)(wr + 20);
            u64 wnv = *(const u64*)(wr + 40);
            fma2(ar[0], a0, wrv); fma2(ar[1], a1p, wrv);
            fma2(ar[2], a2, wrv); fma2(ar[3], a3, wrv);
            fma2(az[0], a0, wzv); fma2(az[1], a1p, wzv);
            fma2(az[2], a2, wzv); fma2(az[3], a3, wzv);
            fma2(an[0], a0, wnv); fma2(an[1], a1p, wnv);
            fma2(an[2], a2, wnv); fma2(an[3], a3, wnv);
        }
        int c = d0 + cl;
        float4 gr0 = *(const float4*)(GIT + (size_t)c * N_NODES + rowoff);
        float4 gr1 = *(const float4*)(GIT + (size_t)(c + 1) * N_NODES + rowoff);
        float4 gz0 = *(const float4*)(GIT + (size_t)(HDIM + c) * N_NODES + rowoff);
        float4 gz1 = *(const float4*)(GIT + (size_t)(HDIM + c + 1) * N_NODES + rowoff);
        float4 gn0 = *(const float4*)(GIT + (size_t)(2 * HDIM + c) * N_NODES + rowoff);
        float4 gn1 = *(const float4*)(GIT + (size_t)(2 * HDIM + c + 1) * N_NODES + rowoff);
        float4 h0 = *(const float4*)(sxT + c * SXS + lane * 4);
        float4 h1 = *(const float4*)(sxT + (c + 1) * SXS + lane * 4);
        float4 o0, o1;
        {
            const float* grp0 = &gr0.x; const float* grp1 = &gr1.x;
            const float* gzp0 = &gz0.x; const float* gzp1 = &gz1.x;
            const float* gnp0 = &gn0.x; const float* gnp1 = &gn1.x;
            const float* hp0 = &h0.x;  const float* hp1 = &h1.x;
            float* op0 = &o0.x; float* op1 = &o1.x;
            #pragma unroll
            for (int r = 0; r < 4; r++) {
                float2 hr = unpack2(ar[r]);
                float2 hz = unpack2(az[r]);
                float2 hn = unpack2(an[r]);
                float r0 = fsigmoid(grp0[r] + hr.x);
                float r1 = fsigmoid(grp1[r] + hr.y);
                float z0 = fsigmoid(gzp0[r] + hz.x);
                float z1 = fsigmoid(gzp1[r] + hz.y);
                float n0 = ftanh_(gnp0[r] + r0 * hn.x);
                float n1 = ftanh_(gnp1[r] + r1 * hn.y);
                op0[r] = (1.0f - z0) * n0 + z0 * hp0[r];
                op1[r] = (1.0f - z1) * n1 + z1 * hp1[r];
            }
        }
        *(float4*)(HoutT + (size_t)c * N_NODES + rowoff) = o0;
        *(float4*)(HoutT + (size_t)(c + 1) * N_NODES + rowoff) = o1;
    }
}

// ---------------- SpMM scatter: msg[dst[e]] += m[src[e]] (row-major) ------------
__global__ void spmm_kernel(const int* __restrict__ dst, const int* __restrict__ src,
                            const float* __restrict__ m, float* __restrict__ msg) {
    long long idx = (long long)blockIdx.x * blockDim.x + threadIdx.x;
    if (idx >= (long long)N_EDGES * 25) return;
    int e = (int)(idx / 25);
    int c = (int)(idx - (long long)e * 25);
    int d = dst[e];
    int s = src[e];
    float4 v = *(const float4*)(m + (size_t)s * HDIM + c * 4);
    float* p = msg + (size_t)d * HDIM + c * 4;
    asm volatile("red.global.add.v4.f32 [%0], {%1, %2, %3, %4};"
                 :: "l"(p), "f"(v.x), "f"(v.y), "f"(v.z), "f"(v.w)
                 : "memory");
}

// ---------------- classifier from transposed h ----------------------------------
__global__ void __launch_bounds__(256) classify_kernel(
    const float* __restrict__ HT,
    const float* __restrict__ w1, const float* __restrict__ b1,
    const float* __restrict__ w2, const float* __restrict__ b2,
    float* __restrict__ out) {
    __shared__ float s1[HDIM * CDIM];
    __shared__ float sb1[CDIM];
    __shared__ float s2[CDIM];
    __shared__ float sb2;
    for (int i = threadIdx.x; i < HDIM * CDIM; i += blockDim.x) s1[i] = w1[i];
    for (int i = threadIdx.x; i < CDIM; i += blockDim.x) { sb1[i] = b1[i]; s2[i] = w2[i]; }
    if (threadIdx.x == 0) sb2 = b2[0];
    __syncthreads();
    int n = blockIdx.x * blockDim.x + threadIdx.x;
    if (n >= N_NODES) return;
    float a[CDIM];
    #pragma unroll
    for (int j = 0; j < CDIM; j++) a[j] = sb1[j];
    for (int k = 0; k < HDIM; k++) {
        float xv = HT[(size_t)k * N_NODES + n];   // coalesced across lanes
        const float* wr = s1 + k * CDIM;
        #pragma unroll
        for (int j = 0; j < CDIM; j++) a[j] = fmaf(xv, wr[j], a[j]);
    }
    float r = sb2;
    #pragma unroll
    for (int j = 0; j < CDIM; j++) r = fmaf(fmaxf(a[j], 0.0f), s2[j], r);
    out[n] = r;
}

// ---------------- host orchestration --------------------------------------------
extern "C" void kernel_launch(void* const* d_in, const int* in_sizes, int n_in,
                              void* d_out, int out_size) {
    const float* features = (const float*)d_in[0];
    const void*  e_row    = d_in[1];
    const void*  e_col    = d_in[2];
    const float* init_w   = (const float*)d_in[3];
    const float* init_b   = (const float*)d_in[4];
    const float* fm_w1 = (const float*)d_in[5],  *fm_b1 = (const float*)d_in[6];
    const float* fm_w2 = (const float*)d_in[7],  *fm_b2 = (const float*)d_in[8];
    const float* bm_w1 = (const float*)d_in[9],  *bm_b1 = (const float*)d_in[10];
    const float* bm_w2 = (const float*)d_in[11], *bm_b2 = (const float*)d_in[12];
    const float* fg_wih = (const float*)d_in[13], *fg_whh = (const float*)d_in[14];
    const float* fg_bih = (const float*)d_in[15], *fg_bhh = (const float*)d_in[16];
    const float* bg_wih = (const float*)d_in[17], *bg_whh = (const float*)d_in[18];
    const float* bg_bih = (const float*)d_in[19], *bg_bhh = (const float*)d_in[20];
    const float* cl_w1 = (const float*)d_in[21], *cl_b1 = (const float*)d_in[22];
    const float* cl_w2 = (const float*)d_in[23], *cl_b2 = (const float*)d_in[24];
    float* out = (float*)d_out;

    float *h, *h2, *m, *msg, *gi;
    int *row_i, *col_i;
    cudaGetSymbolAddress((void**)&h,    g_h);
    cudaGetSymbolAddress((void**)&h2,   g_h2);
    cudaGetSymbolAddress((void**)&m,    g_m);
    cudaGetSymbolAddress((void**)&msg,  g_msg);
    cudaGetSymbolAddress((void**)&gi,   g_gi);
    cudaGetSymbolAddress((void**)&row_i, g_row);
    cudaGetSymbolAddress((void**)&col_i, g_col);

    const size_t smem_mlp  = (size_t)(HDIM * SXS + 5000 + 5000 + 150) * sizeof(float); // 93,400
    const size_t smem_gi   = (size_t)(HDIM * SXS + 10000 + 300) * sizeof(float);       // 94,000
    const size_t smem_gate = (size_t)(HDIM * SXS + 6000 + 300) * sizeof(float);        // 78,000
    cudaFuncSetAttribute(mlp_tiled,  cudaFuncAttributeMaxDynamicSharedMemorySize, (int)smem_mlp);
    cudaFuncSetAttribute(gi_tiled,   cudaFuncAttributeMaxDynamicSharedMemorySize, (int)smem_gi);
    cudaFuncSetAttribute(gate_tiled, cudaFuncAttributeMaxDynamicSharedMemorySize, (int)smem_gate);

    const int GT   = N_NODES / MTILE;            // 3125 (exact)
    const int GN256 = (N_NODES + 255) / 256;
    const int GE   = (N_EDGES + 255) / 256;
    const int GE25 = (int)(((long long)N_EDGES * 25 + 255) / 256);

    detect_kernel<<<1, 32>>>((const unsigned int*)e_row);
    convert_kernel<<<GE, 256>>>(e_row, e_col, row_i, col_i);
    initT_kernel<<<GT, MTILE>>>(features, init_w, init_b, h);

    float* hc = h;
    float* hn = h2;
    const size_t msg_bytes = (size_t)N_NODES * HDIM * sizeof(float);

    for (int rnd = 0; rnd < 20; rnd++) {
        // forward pass
        mlp_tiled<<<GT, GTB, smem_mlp>>>(hc, fm_w1, fm_b1, fm_w2, fm_b2, m);
        cudaMemsetAsync(msg, 0, msg_bytes);
        spmm_kernel<<<GE25, 256>>>(row_i, col_i, m, msg);   // msg[row] += m[col]
        gi_tiled<<<GT, GTB, smem_gi>>>(msg, fg_wih, fg_bih, gi);
        gate_tiled<<<GT, GTB, smem_gate>>>(gi, hc, fg_whh, fg_bhh, hn);
        { float* t = hc; hc = hn; hn = t; }
        // backward pass
        mlp_tiled<<<GT, GTB, smem_mlp>>>(hc, bm_w1, bm_b1, bm_w2, bm_b2, m);
        cudaMemsetAsync(msg, 0, msg_bytes);
        spmm_kernel<<<GE25, 256>>>(col_i, row_i, m, msg);   // msg[col] += m[row]
        gi_tiled<<<GT, GTB, smem_gi>>>(msg, bg_wih, bg_bih, gi);
        gate_tiled<<<GT, GTB, smem_gate>>>(gi, hc, bg_whh, bg_bhh, hn);
        { float* t = hc; hc = hn; hn = t; }
    }

    classify_kernel<<<GN256, 256>>>(hc, cl_w1, cl_b1, cl_w2, cl_b2, out);
}